// round 11
// baseline (speedup 1.0000x reference)
#include <cuda_runtime.h>

#define BB   4
#define HH   256
#define WW   256
#define CC   64
#define CIN  3
#define OFFC 18
#define OFFP 20
#define NP   16

// Scratch (allocation-free)
__device__ float4 g_feat[NP * BB * HH * WW];       // NC4HW4 features
__device__ float  g_off [BB * HH * WW * OFFC];     // NHWC offsets
__device__ float  g_cwT [CIN * 9 * CC];
__device__ float  g_owT [CC * 9 * OFFP];
__device__ float  g_dwT [9 * CC * CC];             // [k][c][o]

typedef unsigned long long ull;

__device__ __forceinline__ ull pack2(float lo, float hi) {
    ull r; asm("mov.b64 %0, {%1,%2};" : "=l"(r) : "f"(lo), "f"(hi)); return r;
}
__device__ __forceinline__ float2 unpack2(ull v) {
    float2 r; asm("mov.b64 {%0,%1}, %2;" : "=f"(r.x), "=f"(r.y) : "l"(v)); return r;
}
#define FMA2(a, x, y) asm("fma.rn.f32x2 %0, %1, %2, %0;" : "+l"(a) : "l"(x), "l"(y))
#define MUL2(a, x, y) asm("mul.rn.f32x2 %0, %1, %2;" : "=l"(a) : "l"(x), "l"(y))

// ---------------------------------------------------------------------------
__global__ void prep_kernel(const float* __restrict__ cw,
                            const float* __restrict__ ow,
                            const float* __restrict__ dw) {
    int t = blockIdx.x * blockDim.x + threadIdx.x;
    int nt = gridDim.x * blockDim.x;
    for (int idx = t; idx < CIN * 9 * CC; idx += nt) {
        int o = idx % CC, r = idx / CC;
        g_cwT[idx] = cw[o * (CIN * 9) + r];
    }
    for (int idx = t; idx < CC * 9 * OFFP; idx += nt) {
        int oc = idx % OFFP, ct = idx / OFFP;
        g_owT[idx] = (oc < OFFC) ? ow[oc * (CC * 9) + ct] : 0.0f;
    }
    for (int idx = t; idx < 9 * CC * CC; idx += nt) {
        int o = idx % CC, c = (idx / CC) % CC, k = idx / (CC * CC);
        g_dwT[idx] = dw[(o * CC + c) * 9 + k];
    }
}

// ---------------------------------------------------------------------------
// Kernel 1: x NCHW -> feat NC4HW4, 3x3 conv pad 1
// ---------------------------------------------------------------------------
__global__ void __launch_bounds__(256) conv_in_kernel(const float* __restrict__ x,
                                                      const float* __restrict__ cb) {
    __shared__ __align__(16) float sw[CIN * 9 * CC];
    __shared__ float sb[CC];
    for (int idx = threadIdx.x; idx < CIN * 9 * CC; idx += 256) sw[idx] = g_cwT[idx];
    if (threadIdx.x < CC) sb[threadIdx.x] = cb[threadIdx.x];
    __syncthreads();

    const int b = blockIdx.x / HH, h = blockIdx.x % HH, w = threadIdx.x;

    ull acc[32];
    #pragma unroll
    for (int q = 0; q < 32; q++) acc[q] = pack2(sb[2 * q], sb[2 * q + 1]);

    #pragma unroll 1
    for (int ci = 0; ci < CIN; ci++) {
        #pragma unroll
        for (int i = 0; i < 3; i++) {
            int y = h - 1 + i;
            bool yv = ((unsigned)y < HH);
            #pragma unroll
            for (int j = 0; j < 3; j++) {
                int xx = w - 1 + j;
                float v = (yv && (unsigned)xx < WW) ? x[((b * CIN + ci) * HH + y) * WW + xx] : 0.0f;
                ull s2 = pack2(v, v);
                const ulonglong2* wp = (const ulonglong2*)&sw[(ci * 9 + i * 3 + j) * CC];
                #pragma unroll
                for (int q = 0; q < 16; q++) {
                    ulonglong2 ww = wp[q];
                    FMA2(acc[2 * q], s2, ww.x);
                    FMA2(acc[2 * q + 1], s2, ww.y);
                }
            }
        }
    }

    const int ppix = h * WW + w;
    #pragma unroll
    for (int q4 = 0; q4 < NP; q4++) {
        float2 lo = unpack2(acc[2 * q4]);
        float2 hi = unpack2(acc[2 * q4 + 1]);
        g_feat[(q4 * BB + b) * HH * WW + ppix] = make_float4(lo.x, lo.y, hi.x, hi.y);
    }
}

// ---------------------------------------------------------------------------
// Kernel 2: feat NC4HW4 -> offsets NHWC(18), 2 rows per block
// ---------------------------------------------------------------------------
__global__ void __launch_bounds__(256) conv_off_kernel(const float* __restrict__ ob) {
    __shared__ __align__(16) float sw[CC * 9 * OFFP];
    for (int idx = threadIdx.x; idx < CC * 9 * OFFP; idx += 256) sw[idx] = g_owT[idx];
    __syncthreads();

    const int b = blockIdx.x / (HH / 2);
    const int h0 = (blockIdx.x % (HH / 2)) * 2;
    const int w = threadIdx.x;

    ull accA[9], accB[9];
    #pragma unroll
    for (int q = 0; q < 9; q++) {
        ull t = pack2(ob[2 * q], ob[2 * q + 1]);
        accA[q] = t; accB[q] = t;
    }

    #pragma unroll 1
    for (int i = 0; i < 3; i++) {
        int yA = h0 - 1 + i, yB = h0 + i;
        bool yAv = ((unsigned)yA < HH), yBv = ((unsigned)yB < HH);
        #pragma unroll 1
        for (int j = 0; j < 3; j++) {
            int xx = w - 1 + j;
            bool xv = ((unsigned)xx < WW);
            bool vA = yAv && xv, vB = yBv && xv;
            int xc = xv ? xx : 0;
            int iA = (vA ? yA : 0) * WW + xc;
            int iB = (vB ? yB : 0) * WW + xc;
            const int tap = i * 3 + j;
            #pragma unroll 1
            for (int c4 = 0; c4 < NP; c4++) {
                const float4* pc = g_feat + (c4 * BB + b) * HH * WW;
                float4 fa = vA ? pc[iA] : make_float4(0.f, 0.f, 0.f, 0.f);
                float4 fb = vB ? pc[iB] : make_float4(0.f, 0.f, 0.f, 0.f);
                const float fav[4] = {fa.x, fa.y, fa.z, fa.w};
                const float fbv[4] = {fb.x, fb.y, fb.z, fb.w};
                #pragma unroll
                for (int cc = 0; cc < 4; cc++) {
                    ull sa = pack2(fav[cc], fav[cc]);
                    ull sb2 = pack2(fbv[cc], fbv[cc]);
                    const float* wrow = &sw[((c4 * 4 + cc) * 9 + tap) * OFFP];
                    const ulonglong2* wp = (const ulonglong2*)wrow;
                    #pragma unroll
                    for (int q2 = 0; q2 < 4; q2++) {
                        ulonglong2 ww = wp[q2];
                        FMA2(accA[2 * q2], sa, ww.x);
                        FMA2(accA[2 * q2 + 1], sa, ww.y);
                        FMA2(accB[2 * q2], sb2, ww.x);
                        FMA2(accB[2 * q2 + 1], sb2, ww.y);
                    }
                    ull w8 = *(const ull*)(wrow + 16);
                    FMA2(accA[8], sa, w8);
                    FMA2(accB[8], sb2, w8);
                }
            }
        }
    }

    float* opA = &g_off[((b * HH + h0) * WW + w) * OFFC];
    float* opB = opA + WW * OFFC;
    #pragma unroll
    for (int q = 0; q < 9; q++) {
        ((float2*)opA)[q] = unpack2(accA[q]);
        ((float2*)opB)[q] = unpack2(accB[q]);
    }
}

// ---------------------------------------------------------------------------
// Kernel 3: deform conv, warp-specialized staged GEMM.
// 192 threads: warps 0-3 = consumers (pure GEMM, 128px x 16o each),
// warps 4-5 = producers (gather + bilinear + W staging).
// S and W double-buffered (96KB smem), ONE __syncthreads per tap:
// tap k: consumers GEMM buf[k&1] while producers fill buf[(k+1)&1].
// ---------------------------------------------------------------------------
__device__ __forceinline__ void tap_coords(int h, int w_img, int kk, float2 o2,
                                           float& w00, float& w01, float& w10, float& w11,
                                           int& i00, int& i01, int& i10, int& i11) {
    const int i = kk / 3, j = kk - 3 * i;
    float sy = (float)(h - 1 + i) + o2.x;
    float sx = (float)(w_img - 1 + j) + o2.y;
    float y0f = floorf(sy), x0f = floorf(sx);
    float dy = sy - y0f, dx = sx - x0f;
    int y0 = (int)y0f, x0 = (int)x0f, y1 = y0 + 1, x1 = x0 + 1;
    bool vy0 = ((unsigned)y0 < HH), vy1 = ((unsigned)y1 < HH);
    bool vx0 = ((unsigned)x0 < WW), vx1 = ((unsigned)x1 < WW);
    w00 = (1.f - dy) * (1.f - dx) * ((vy0 && vx0) ? 1.f : 0.f);
    w01 = (1.f - dy) * dx         * ((vy0 && vx1) ? 1.f : 0.f);
    w10 = dy * (1.f - dx)         * ((vy1 && vx0) ? 1.f : 0.f);
    w11 = dy * dx                 * ((vy1 && vx1) ? 1.f : 0.f);
    int y0c = min(max(y0, 0), HH - 1), y1c = min(max(y1, 0), HH - 1);
    int x0c = min(max(x0, 0), WW - 1), x1c = min(max(x1, 0), WW - 1);
    i00 = y0c * WW + x0c; i01 = y0c * WW + x1c;
    i10 = y1c * WW + x0c; i11 = y1c * WW + x1c;
}

__device__ __forceinline__ void gather_tap(float* Sd, int b, int h, int w_img,
                                           int px, int k, const float* offp) {
    float2 o2 = __ldg((const float2*)(offp + 2 * k));
    float w00, w01, w10, w11; int i00, i01, i10, i11;
    tap_coords(h, w_img, k, o2, w00, w01, w10, w11, i00, i01, i10, i11);
    ull W00 = pack2(w00, w00), W01 = pack2(w01, w01);
    ull W10 = pack2(w10, w10), W11 = pack2(w11, w11);
    #pragma unroll
    for (int pl = 0; pl < NP; pl++) {
        const ulonglong2* pc = (const ulonglong2*)(g_feat + (pl * BB + b) * HH * WW);
        ulonglong2 a = pc[i00], b2 = pc[i01], c2 = pc[i10], d2 = pc[i11];
        ull s01, s23;
        MUL2(s01, W00, a.x);
        FMA2(s01, W01, b2.x); FMA2(s01, W10, c2.x); FMA2(s01, W11, d2.x);
        MUL2(s23, W00, a.y);
        FMA2(s23, W01, b2.y); FMA2(s23, W10, c2.y); FMA2(s23, W11, d2.y);
        float2 u01 = unpack2(s01), u23 = unpack2(s23);
        const int cb = pl * 4;
        Sd[(cb + 0) * 128 + px] = u01.x;
        Sd[(cb + 1) * 128 + px] = u01.y;
        Sd[(cb + 2) * 128 + px] = u23.x;
        Sd[(cb + 3) * 128 + px] = u23.y;
    }
}

__global__ void __launch_bounds__(192, 2) deform_kernel(const float* __restrict__ db,
                                                        float* __restrict__ out) {
    extern __shared__ __align__(16) float smem[];
    float* S0 = smem;              // 8192 floats
    float* S1 = smem + 8192;
    float* W0 = smem + 16384;      // 4096 floats
    float* W1 = smem + 20480;

    const int tid = threadIdx.x;
    const int bi = blockIdx.x;
    const int b = bi >> 9;
    const int rest = bi & 511;
    const int h = rest >> 1;
    const int wbase = (rest & 1) << 7;

    const bool producer = (tid >= 128);
    const int lane = tid & 31;
    const int o_t = tid >> 5;             // consumers: 0..3

    if (producer) {
        // ---- producer path: 64 threads, 2 pixels each ----
        const int ptid = tid - 128;       // 0..63
        const int px0 = ptid, px1 = ptid + 64;
        const int wi0 = wbase + px0, wi1 = wbase + px1;
        const float* offp0 = g_off + (((b * HH + h) * WW) + wi0) * OFFC;
        const float* offp1 = g_off + (((b * HH + h) * WW) + wi1) * OFFC;

        // prologue: W(0) + S(0) into buffer 0
        {
            const float4* gWk = (const float4*)(g_dwT);
            #pragma unroll
            for (int q = 0; q < 16; q++)
                ((float4*)W0)[q * 64 + ptid] = gWk[q * 64 + ptid];
            gather_tap(S0, b, h, wi0, px0, 0, offp0);
            gather_tap(S0, b, h, wi1, px1, 0, offp1);
        }
        __syncthreads();

        #pragma unroll 1
        for (int k = 0; k < 9; k++) {
            const int kk = k + 1;
            if (kk < 9) {
                float* Sd = (kk & 1) ? S1 : S0;
                float4* Wd = (float4*)((kk & 1) ? W1 : W0);
                const float4* gWk = (const float4*)(g_dwT + kk * CC * CC);
                #pragma unroll
                for (int q = 0; q < 16; q++)
                    Wd[q * 64 + ptid] = gWk[q * 64 + ptid];
                gather_tap(Sd, b, h, wi0, px0, kk, offp0);
                gather_tap(Sd, b, h, wi1, px1, kk, offp1);
            }
            __syncthreads();
        }
    } else {
        // ---- consumer path: 4 warps, pure GEMM ----
        __syncthreads();   // wait for prologue fill

        ull acc[4][8];
        #pragma unroll
        for (int pp = 0; pp < 4; pp++)
            #pragma unroll
            for (int op = 0; op < 8; op++) acc[pp][op] = 0ull;

        #pragma unroll 1
        for (int k = 0; k < 9; k++) {
            const float* Sb = (k & 1) ? S1 : S0;
            const float* Wb = (k & 1) ? W1 : W0;

            #pragma unroll 4
            for (int c = 0; c < CC; c++) {
                float4 sv = *(const float4*)(Sb + c * 128 + lane * 4);
                const ulonglong2* wrow = (const ulonglong2*)(Wb + c * 64 + o_t * 16);
                ulonglong2 wA = wrow[0];
                ulonglong2 wB = wrow[1];
                ulonglong2 wC = wrow[2];
                ulonglong2 wD = wrow[3];
                ull s;
                s = pack2(sv.x, sv.x);
                FMA2(acc[0][0], s, wA.x); FMA2(acc[0][1], s, wA.y);
                FMA2(acc[0][2], s, wB.x); FMA2(acc[0][3], s, wB.y);
                FMA2(acc[0][4], s, wC.x); FMA2(acc[0][5], s, wC.y);
                FMA2(acc[0][6], s, wD.x); FMA2(acc[0][7], s, wD.y);
                s = pack2(sv.y, sv.y);
                FMA2(acc[1][0], s, wA.x); FMA2(acc[1][1], s, wA.y);
                FMA2(acc[1][2], s, wB.x); FMA2(acc[1][3], s, wB.y);
                FMA2(acc[1][4], s, wC.x); FMA2(acc[1][5], s, wC.y);
                FMA2(acc[1][6], s, wD.x); FMA2(acc[1][7], s, wD.y);
                s = pack2(sv.z, sv.z);
                FMA2(acc[2][0], s, wA.x); FMA2(acc[2][1], s, wA.y);
                FMA2(acc[2][2], s, wB.x); FMA2(acc[2][3], s, wB.y);
                FMA2(acc[2][4], s, wC.x); FMA2(acc[2][5], s, wC.y);
                FMA2(acc[2][6], s, wD.x); FMA2(acc[2][7], s, wD.y);
                s = pack2(sv.w, sv.w);
                FMA2(acc[3][0], s, wA.x); FMA2(acc[3][1], s, wA.y);
                FMA2(acc[3][2], s, wB.x); FMA2(acc[3][3], s, wB.y);
                FMA2(acc[3][4], s, wC.x); FMA2(acc[3][5], s, wC.y);
                FMA2(acc[3][6], s, wD.x); FMA2(acc[3][7], s, wD.y);
            }
            __syncthreads();
        }

        // epilogue: add bias, write NCHW
        const float2* db2 = (const float2*)db;
        const int wOff = o_t * 16;
        #pragma unroll
        for (int op = 0; op < 8; op++) {
            float2 bz = db2[o_t * 8 + op];
            const int o = wOff + op * 2;
            #pragma unroll
            for (int pp = 0; pp < 4; pp++) {
                float2 v = unpack2(acc[pp][op]);
                const int base = ((b * CC + o) * HH + h) * WW + wbase + lane * 4 + pp;
                out[base] = v.x + bz.x;
                out[base + HH * WW] = v.y + bz.y;
            }
        }
    }
}

// ---------------------------------------------------------------------------
extern "C" void kernel_launch(void* const* d_in, const int* in_sizes, int n_in,
                              void* d_out, int out_size) {
    const float* x        = (const float*)d_in[0];
    const float* conv_w   = (const float*)d_in[1];
    const float* conv_b   = (const float*)d_in[2];
    const float* offset_w = (const float*)d_in[3];
    const float* offset_b = (const float*)d_in[4];
    const float* deform_w = (const float*)d_in[5];
    const float* deform_b = (const float*)d_in[6];
    float* out = (float*)d_out;

    const int dsm = 24576 * (int)sizeof(float);   // 96KB
    cudaFuncSetAttribute(deform_kernel, cudaFuncAttributeMaxDynamicSharedMemorySize, dsm);

    prep_kernel<<<96, 512>>>(conv_w, offset_w, deform_w);
    conv_in_kernel<<<BB * HH, 256>>>(x, conv_b);
    conv_off_kernel<<<BB * HH / 2, 256>>>(offset_b);
    deform_kernel<<<BB * HH * 2, 192, dsm>>>(deform_b, out);
}

// round 12
// speedup vs baseline: 1.5740x; 1.5740x over previous
#include <cuda_runtime.h>

#define BB   4
#define HH   256
#define WW   256
#define CC   64
#define CIN  3
#define OFFC 18
#define OFFP 20
#define NP   16

// Scratch (allocation-free)
__device__ float4 g_feat[NP * BB * HH * WW];       // NC4HW4 features
__device__ float  g_off [BB * HH * WW * OFFC];     // NHWC offsets
__device__ float  g_cwT [CIN * 9 * CC];
__device__ float  g_owT [CC * 9 * OFFP];
__device__ float  g_dwT [9 * CC * CC];             // [k][c][o]

typedef unsigned long long ull;

__device__ __forceinline__ ull pack2(float lo, float hi) {
    ull r; asm("mov.b64 %0, {%1,%2};" : "=l"(r) : "f"(lo), "f"(hi)); return r;
}
__device__ __forceinline__ float2 unpack2(ull v) {
    float2 r; asm("mov.b64 {%0,%1}, %2;" : "=f"(r.x), "=f"(r.y) : "l"(v)); return r;
}
#define FMA2(a, x, y) asm("fma.rn.f32x2 %0, %1, %2, %0;" : "+l"(a) : "l"(x), "l"(y))
#define MUL2(a, x, y) asm("mul.rn.f32x2 %0, %1, %2;" : "=l"(a) : "l"(x), "l"(y))

// ---------------------------------------------------------------------------
__global__ void prep_kernel(const float* __restrict__ cw,
                            const float* __restrict__ ow,
                            const float* __restrict__ dw) {
    int t = blockIdx.x * blockDim.x + threadIdx.x;
    int nt = gridDim.x * blockDim.x;
    for (int idx = t; idx < CIN * 9 * CC; idx += nt) {
        int o = idx % CC, r = idx / CC;
        g_cwT[idx] = cw[o * (CIN * 9) + r];
    }
    for (int idx = t; idx < CC * 9 * OFFP; idx += nt) {
        int oc = idx % OFFP, ct = idx / OFFP;
        g_owT[idx] = (oc < OFFC) ? ow[oc * (CC * 9) + ct] : 0.0f;
    }
    for (int idx = t; idx < 9 * CC * CC; idx += nt) {
        int o = idx % CC, c = (idx / CC) % CC, k = idx / (CC * CC);
        g_dwT[idx] = dw[(o * CC + c) * 9 + k];
    }
}

// ---------------------------------------------------------------------------
// Kernel 1: x NCHW -> feat NC4HW4, 3x3 conv pad 1
// ---------------------------------------------------------------------------
__global__ void __launch_bounds__(256) conv_in_kernel(const float* __restrict__ x,
                                                      const float* __restrict__ cb) {
    __shared__ __align__(16) float sw[CIN * 9 * CC];
    __shared__ float sb[CC];
    for (int idx = threadIdx.x; idx < CIN * 9 * CC; idx += 256) sw[idx] = g_cwT[idx];
    if (threadIdx.x < CC) sb[threadIdx.x] = cb[threadIdx.x];
    __syncthreads();

    const int b = blockIdx.x / HH, h = blockIdx.x % HH, w = threadIdx.x;

    ull acc[32];
    #pragma unroll
    for (int q = 0; q < 32; q++) acc[q] = pack2(sb[2 * q], sb[2 * q + 1]);

    #pragma unroll 1
    for (int ci = 0; ci < CIN; ci++) {
        #pragma unroll
        for (int i = 0; i < 3; i++) {
            int y = h - 1 + i;
            bool yv = ((unsigned)y < HH);
            #pragma unroll
            for (int j = 0; j < 3; j++) {
                int xx = w - 1 + j;
                float v = (yv && (unsigned)xx < WW) ? x[((b * CIN + ci) * HH + y) * WW + xx] : 0.0f;
                ull s2 = pack2(v, v);
                const ulonglong2* wp = (const ulonglong2*)&sw[(ci * 9 + i * 3 + j) * CC];
                #pragma unroll
                for (int q = 0; q < 16; q++) {
                    ulonglong2 ww = wp[q];
                    FMA2(acc[2 * q], s2, ww.x);
                    FMA2(acc[2 * q + 1], s2, ww.y);
                }
            }
        }
    }

    const int ppix = h * WW + w;
    #pragma unroll
    for (int q4 = 0; q4 < NP; q4++) {
        float2 lo = unpack2(acc[2 * q4]);
        float2 hi = unpack2(acc[2 * q4 + 1]);
        g_feat[(q4 * BB + b) * HH * WW + ppix] = make_float4(lo.x, lo.y, hi.x, hi.y);
    }
}

// ---------------------------------------------------------------------------
// Kernel 2: feat NC4HW4 -> offsets NHWC(18), 2 rows per block
// ---------------------------------------------------------------------------
__global__ void __launch_bounds__(256) conv_off_kernel(const float* __restrict__ ob) {
    __shared__ __align__(16) float sw[CC * 9 * OFFP];
    for (int idx = threadIdx.x; idx < CC * 9 * OFFP; idx += 256) sw[idx] = g_owT[idx];
    __syncthreads();

    const int b = blockIdx.x / (HH / 2);
    const int h0 = (blockIdx.x % (HH / 2)) * 2;
    const int w = threadIdx.x;

    ull accA[9], accB[9];
    #pragma unroll
    for (int q = 0; q < 9; q++) {
        ull t = pack2(ob[2 * q], ob[2 * q + 1]);
        accA[q] = t; accB[q] = t;
    }

    #pragma unroll 1
    for (int i = 0; i < 3; i++) {
        int yA = h0 - 1 + i, yB = h0 + i;
        bool yAv = ((unsigned)yA < HH), yBv = ((unsigned)yB < HH);
        #pragma unroll 1
        for (int j = 0; j < 3; j++) {
            int xx = w - 1 + j;
            bool xv = ((unsigned)xx < WW);
            bool vA = yAv && xv, vB = yBv && xv;
            int xc = xv ? xx : 0;
            int iA = (vA ? yA : 0) * WW + xc;
            int iB = (vB ? yB : 0) * WW + xc;
            const int tap = i * 3 + j;
            #pragma unroll 1
            for (int c4 = 0; c4 < NP; c4++) {
                const float4* pc = g_feat + (c4 * BB + b) * HH * WW;
                float4 fa = vA ? pc[iA] : make_float4(0.f, 0.f, 0.f, 0.f);
                float4 fb = vB ? pc[iB] : make_float4(0.f, 0.f, 0.f, 0.f);
                const float fav[4] = {fa.x, fa.y, fa.z, fa.w};
                const float fbv[4] = {fb.x, fb.y, fb.z, fb.w};
                #pragma unroll
                for (int cc = 0; cc < 4; cc++) {
                    ull sa = pack2(fav[cc], fav[cc]);
                    ull sb2 = pack2(fbv[cc], fbv[cc]);
                    const float* wrow = &sw[((c4 * 4 + cc) * 9 + tap) * OFFP];
                    const ulonglong2* wp = (const ulonglong2*)wrow;
                    #pragma unroll
                    for (int q2 = 0; q2 < 4; q2++) {
                        ulonglong2 ww = wp[q2];
                        FMA2(accA[2 * q2], sa, ww.x);
                        FMA2(accA[2 * q2 + 1], sa, ww.y);
                        FMA2(accB[2 * q2], sb2, ww.x);
                        FMA2(accB[2 * q2 + 1], sb2, ww.y);
                    }
                    ull w8 = *(const ull*)(wrow + 16);
                    FMA2(accA[8], sa, w8);
                    FMA2(accB[8], sb2, w8);
                }
            }
        }
    }

    float* opA = &g_off[((b * HH + h0) * WW + w) * OFFC];
    float* opB = opA + WW * OFFC;
    #pragma unroll
    for (int q = 0; q < 9; q++) {
        ((float2*)opA)[q] = unpack2(accA[q]);
        ((float2*)opB)[q] = unpack2(accB[q]);
    }
}

// ---------------------------------------------------------------------------
// Kernel 3: deform conv staged GEMM with per-CTA tap-order rotation.
// 128 threads, 4 warps, warp = 128px x 16o. Single S (32KB) + W (16KB)
// buffers = 48KB -> 3 CTAs/SM. Each CTA starts its tap loop at a different
// k0 so co-resident CTAs are phase-shifted: one CTA's gather (memory) overlaps
// the others' GEMM (fma). Tap sum is order-independent.
// ---------------------------------------------------------------------------
__device__ __forceinline__ void tap_coords(int h, int w_img, int kk, float2 o2,
                                           float& w00, float& w01, float& w10, float& w11,
                                           int& i00, int& i01, int& i10, int& i11) {
    const int i = kk / 3, j = kk - 3 * i;
    float sy = (float)(h - 1 + i) + o2.x;
    float sx = (float)(w_img - 1 + j) + o2.y;
    float y0f = floorf(sy), x0f = floorf(sx);
    float dy = sy - y0f, dx = sx - x0f;
    int y0 = (int)y0f, x0 = (int)x0f, y1 = y0 + 1, x1 = x0 + 1;
    bool vy0 = ((unsigned)y0 < HH), vy1 = ((unsigned)y1 < HH);
    bool vx0 = ((unsigned)x0 < WW), vx1 = ((unsigned)x1 < WW);
    w00 = (1.f - dy) * (1.f - dx) * ((vy0 && vx0) ? 1.f : 0.f);
    w01 = (1.f - dy) * dx         * ((vy0 && vx1) ? 1.f : 0.f);
    w10 = dy * (1.f - dx)         * ((vy1 && vx0) ? 1.f : 0.f);
    w11 = dy * dx                 * ((vy1 && vx1) ? 1.f : 0.f);
    int y0c = min(max(y0, 0), HH - 1), y1c = min(max(y1, 0), HH - 1);
    int x0c = min(max(x0, 0), WW - 1), x1c = min(max(x1, 0), WW - 1);
    i00 = y0c * WW + x0c; i01 = y0c * WW + x1c;
    i10 = y1c * WW + x0c; i11 = y1c * WW + x1c;
}

__global__ void __launch_bounds__(128, 3) deform_kernel(const float* __restrict__ db,
                                                        float* __restrict__ out) {
    extern __shared__ __align__(16) float smem[];
    float* Sb = smem;             // 8192 floats (S[64][128], 32KB)
    float* Wb = smem + 8192;      // 4096 floats (W[64][64], 16KB)

    const int tid = threadIdx.x;
    const int bi = blockIdx.x;
    const int b = bi >> 9;
    const int rest = bi & 511;
    const int h = rest >> 1;
    const int wbase = (rest & 1) << 7;

    const int px_g = tid;                 // gather pixel (0..127)
    const int w_img = wbase + px_g;

    const int lane = tid & 31;
    const int o_t = tid >> 5;             // 0..3 (16 outputs each)

    // Phase-rotation: co-resident CTAs (consecutive bids) start at different taps.
    const int k0 = (bi % 3) * 3;

    const float* offp = g_off + (((b * HH + h) * WW) + w_img) * OFFC;

    ull acc[4][8];
    #pragma unroll
    for (int pp = 0; pp < 4; pp++)
        #pragma unroll
        for (int op = 0; op < 8; op++) acc[pp][op] = 0ull;

    #pragma unroll 1
    for (int t = 0; t < 9; t++) {
        int k = k0 + t; if (k >= 9) k -= 9;

        __syncthreads();   // previous GEMM done reading Sb/Wb

        // load W tap tile: 1024 float4, 8 per thread
        {
            const float4* gWk = (const float4*)(g_dwT + k * CC * CC);
            #pragma unroll
            for (int q = 0; q < 8; q++)
                ((float4*)Wb)[q * 128 + tid] = gWk[q * 128 + tid];
        }
        // gather + bilinear into S
        {
            float2 o2 = __ldg((const float2*)(offp + 2 * k));
            float w00, w01, w10, w11; int i00, i01, i10, i11;
            tap_coords(h, w_img, k, o2, w00, w01, w10, w11, i00, i01, i10, i11);
            ull W00 = pack2(w00, w00), W01 = pack2(w01, w01);
            ull W10 = pack2(w10, w10), W11 = pack2(w11, w11);
            #pragma unroll
            for (int pl = 0; pl < NP; pl++) {
                const ulonglong2* pc = (const ulonglong2*)(g_feat + (pl * BB + b) * HH * WW);
                ulonglong2 a = pc[i00], b2 = pc[i01], c2 = pc[i10], d2 = pc[i11];
                ull s01, s23;
                MUL2(s01, W00, a.x);
                FMA2(s01, W01, b2.x); FMA2(s01, W10, c2.x); FMA2(s01, W11, d2.x);
                MUL2(s23, W00, a.y);
                FMA2(s23, W01, b2.y); FMA2(s23, W10, c2.y); FMA2(s23, W11, d2.y);
                float2 u01 = unpack2(s01), u23 = unpack2(s23);
                const int cb = pl * 4;
                Sb[(cb + 0) * 128 + px_g] = u01.x;
                Sb[(cb + 1) * 128 + px_g] = u01.y;
                Sb[(cb + 2) * 128 + px_g] = u23.x;
                Sb[(cb + 3) * 128 + px_g] = u23.y;
            }
        }
        __syncthreads();

        // GEMM: acc[4px][16o] += S[c][4px] * W[c][16o]
        #pragma unroll 4
        for (int c = 0; c < CC; c++) {
            float4 sv = *(const float4*)(Sb + c * 128 + lane * 4);
            const ulonglong2* wrow = (const ulonglong2*)(Wb + c * 64 + o_t * 16);
            ulonglong2 wA = wrow[0];
            ulonglong2 wB = wrow[1];
            ulonglong2 wC = wrow[2];
            ulonglong2 wD = wrow[3];
            ull s;
            s = pack2(sv.x, sv.x);
            FMA2(acc[0][0], s, wA.x); FMA2(acc[0][1], s, wA.y);
            FMA2(acc[0][2], s, wB.x); FMA2(acc[0][3], s, wB.y);
            FMA2(acc[0][4], s, wC.x); FMA2(acc[0][5], s, wC.y);
            FMA2(acc[0][6], s, wD.x); FMA2(acc[0][7], s, wD.y);
            s = pack2(sv.y, sv.y);
            FMA2(acc[1][0], s, wA.x); FMA2(acc[1][1], s, wA.y);
            FMA2(acc[1][2], s, wB.x); FMA2(acc[1][3], s, wB.y);
            FMA2(acc[1][4], s, wC.x); FMA2(acc[1][5], s, wC.y);
            FMA2(acc[1][6], s, wD.x); FMA2(acc[1][7], s, wD.y);
            s = pack2(sv.z, sv.z);
            FMA2(acc[2][0], s, wA.x); FMA2(acc[2][1], s, wA.y);
            FMA2(acc[2][2], s, wB.x); FMA2(acc[2][3], s, wB.y);
            FMA2(acc[2][4], s, wC.x); FMA2(acc[2][5], s, wC.y);
            FMA2(acc[2][6], s, wD.x); FMA2(acc[2][7], s, wD.y);
            s = pack2(sv.w, sv.w);
            FMA2(acc[3][0], s, wA.x); FMA2(acc[3][1], s, wA.y);
            FMA2(acc[3][2], s, wB.x); FMA2(acc[3][3], s, wB.y);
            FMA2(acc[3][4], s, wC.x); FMA2(acc[3][5], s, wC.y);
            FMA2(acc[3][6], s, wD.x); FMA2(acc[3][7], s, wD.y);
        }
    }

    // Epilogue: add bias, write NCHW
    const float2* db2 = (const float2*)db;
    const int wOff = o_t * 16;
    #pragma unroll
    for (int op = 0; op < 8; op++) {
        float2 bz = db2[o_t * 8 + op];
        const int o = wOff + op * 2;
        #pragma unroll
        for (int pp = 0; pp < 4; pp++) {
            float2 v = unpack2(acc[pp][op]);
            const int base = ((b * CC + o) * HH + h) * WW + wbase + lane * 4 + pp;
            out[base] = v.x + bz.x;
            out[base + HH * WW] = v.y + bz.y;
        }
    }
}

// ---------------------------------------------------------------------------
extern "C" void kernel_launch(void* const* d_in, const int* in_sizes, int n_in,
                              void* d_out, int out_size) {
    const float* x        = (const float*)d_in[0];
    const float* conv_w   = (const float*)d_in[1];
    const float* conv_b   = (const float*)d_in[2];
    const float* offset_w = (const float*)d_in[3];
    const float* offset_b = (const float*)d_in[4];
    const float* deform_w = (const float*)d_in[5];
    const float* deform_b = (const float*)d_in[6];
    float* out = (float*)d_out;

    const int dsm = 12288 * (int)sizeof(float);   // 48KB
    cudaFuncSetAttribute(deform_kernel, cudaFuncAttributeMaxDynamicSharedMemorySize, dsm);

    prep_kernel<<<96, 512>>>(conv_w, offset_w, deform_w);
    conv_in_kernel<<<BB * HH, 256>>>(x, conv_b);
    conv_off_kernel<<<BB * HH / 2, 256>>>(offset_b);
    deform_kernel<<<BB * HH * 2, 128, dsm>>>(deform_b, out);
}

// round 14
// speedup vs baseline: 1.8624x; 1.1832x over previous
#include <cuda_runtime.h>
#include <cstdint>

#define BB   4
#define HH   256
#define WW   256
#define CC   64
#define CIN  3
#define OFFC 18
#define OFFP 20
#define NP   16

// Scratch (allocation-free)
__device__ float4 g_feat[NP * BB * HH * WW];       // NC4HW4 features
__device__ float  g_off [BB * HH * WW * OFFC];     // NHWC offsets
__device__ float  g_cwT [CIN * 9 * CC];
__device__ float  g_owT [CC * 9 * OFFP];
__device__ unsigned char g_dwB[9 * 16384];         // per tap: 8KB Whi + 8KB Wlo bf16, swizzled

typedef unsigned long long ull;
typedef unsigned int uint32;

__device__ __forceinline__ ull pack2(float lo, float hi) {
    ull r; asm("mov.b64 %0, {%1,%2};" : "=l"(r) : "f"(lo), "f"(hi)); return r;
}
__device__ __forceinline__ float2 unpack2(ull v) {
    float2 r; asm("mov.b64 {%0,%1}, %2;" : "=f"(r.x), "=f"(r.y) : "l"(v)); return r;
}
#define FMA2(a, x, y) asm("fma.rn.f32x2 %0, %1, %2, %0;" : "+l"(a) : "l"(x), "l"(y))
#define MUL2(a, x, y) asm("mul.rn.f32x2 %0, %1, %2;" : "=l"(a) : "l"(x), "l"(y))

__device__ __forceinline__ uint32 smem_u32(const void* p) {
    uint32 a;
    asm("{ .reg .u64 t; cvta.to.shared.u64 t, %1; cvt.u32.u64 %0, t; }" : "=r"(a) : "l"(p));
    return a;
}

#define LDMX4(r0, r1, r2, r3, addr) \
    asm volatile("ldmatrix.sync.aligned.m8n8.x4.shared.b16 {%0,%1,%2,%3}, [%4];" \
                 : "=r"(r0), "=r"(r1), "=r"(r2), "=r"(r3) : "r"(addr))

#define MMA_BF16(d, a0, a1, b0) \
    asm volatile("mma.sync.aligned.m16n8k8.row.col.f32.bf16.bf16.f32 " \
                 "{%0,%1,%2,%3}, {%4,%5}, {%6}, {%0,%1,%2,%3};" \
                 : "+f"((d)[0]), "+f"((d)[1]), "+f"((d)[2]), "+f"((d)[3]) \
                 : "r"(a0), "r"(a1), "r"(b0))

// split packed f32x2 -> bf16x2 hi + bf16x2 lo
__device__ __forceinline__ uint32 bf_split(ull s, uint32& lo) {
    float2 f = unpack2(s);
    uint32 h;
    asm("cvt.rn.bf16x2.f32 %0, %1, %2;" : "=r"(h) : "f"(f.y), "f"(f.x));
    float hf0 = __uint_as_float(h << 16);
    float hf1 = __uint_as_float(h & 0xffff0000u);
    float l0 = f.x - hf0, l1 = f.y - hf1;
    asm("cvt.rn.bf16x2.f32 %0, %1, %2;" : "=r"(lo) : "f"(l1), "f"(l0));
    return h;
}

// ---------------------------------------------------------------------------
__global__ void prep_kernel(const float* __restrict__ cw,
                            const float* __restrict__ ow,
                            const float* __restrict__ dw) {
    int t = blockIdx.x * blockDim.x + threadIdx.x;
    int nt = gridDim.x * blockDim.x;
    for (int idx = t; idx < CIN * 9 * CC; idx += nt) {
        int o = idx % CC, r = idx / CC;
        g_cwT[idx] = cw[o * (CIN * 9) + r];
    }
    for (int idx = t; idx < CC * 9 * OFFP; idx += nt) {
        int oc = idx % OFFP, ct = idx / OFFP;
        g_owT[idx] = (oc < OFFC) ? ow[oc * (CC * 9) + ct] : 0.0f;
    }
    // deform weights -> bf16 hi/lo tiles [k][o row][c col], 16B-granule swizzle
    for (int idx = t; idx < 9 * CC * CC; idx += nt) {
        int k = idx / (CC * CC), r = idx % (CC * CC);
        int o = r / CC, c = r % CC;
        float wv = dw[(o * CC + c) * 9 + k];
        uint32 hb;
        asm("cvt.rn.bf16x2.f32 %0, %1, %2;" : "=r"(hb) : "f"(0.0f), "f"(wv));
        float hf = __uint_as_float(hb << 16);
        float lv = wv - hf;
        uint32 lb;
        asm("cvt.rn.bf16x2.f32 %0, %1, %2;" : "=r"(lb) : "f"(0.0f), "f"(lv));
        int g = c >> 3;
        int byte = o * 128 + ((g ^ (o & 7)) * 16) + (c & 7) * 2;
        *(unsigned short*)(g_dwB + k * 16384 + byte) = (unsigned short)(hb & 0xffff);
        *(unsigned short*)(g_dwB + k * 16384 + 8192 + byte) = (unsigned short)(lb & 0xffff);
    }
}

// ---------------------------------------------------------------------------
// Kernel 1: x NCHW -> feat NC4HW4, 3x3 conv pad 1
// ---------------------------------------------------------------------------
__global__ void __launch_bounds__(256) conv_in_kernel(const float* __restrict__ x,
                                                      const float* __restrict__ cb) {
    __shared__ __align__(16) float sw[CIN * 9 * CC];
    __shared__ float sb[CC];
    for (int idx = threadIdx.x; idx < CIN * 9 * CC; idx += 256) sw[idx] = g_cwT[idx];
    if (threadIdx.x < CC) sb[threadIdx.x] = cb[threadIdx.x];
    __syncthreads();

    const int b = blockIdx.x / HH, h = blockIdx.x % HH, w = threadIdx.x;

    ull acc[32];
    #pragma unroll
    for (int q = 0; q < 32; q++) acc[q] = pack2(sb[2 * q], sb[2 * q + 1]);

    #pragma unroll 1
    for (int ci = 0; ci < CIN; ci++) {
        #pragma unroll
        for (int i = 0; i < 3; i++) {
            int y = h - 1 + i;
            bool yv = ((unsigned)y < HH);
            #pragma unroll
            for (int j = 0; j < 3; j++) {
                int xx = w - 1 + j;
                float v = (yv && (unsigned)xx < WW) ? x[((b * CIN + ci) * HH + y) * WW + xx] : 0.0f;
                ull s2 = pack2(v, v);
                const ulonglong2* wp = (const ulonglong2*)&sw[(ci * 9 + i * 3 + j) * CC];
                #pragma unroll
                for (int q = 0; q < 16; q++) {
                    ulonglong2 ww = wp[q];
                    FMA2(acc[2 * q], s2, ww.x);
                    FMA2(acc[2 * q + 1], s2, ww.y);
                }
            }
        }
    }

    const int ppix = h * WW + w;
    #pragma unroll
    for (int q4 = 0; q4 < NP; q4++) {
        float2 lo = unpack2(acc[2 * q4]);
        float2 hi = unpack2(acc[2 * q4 + 1]);
        g_feat[(q4 * BB + b) * HH * WW + ppix] = make_float4(lo.x, lo.y, hi.x, hi.y);
    }
}

// ---------------------------------------------------------------------------
// Kernel 2: feat NC4HW4 -> offsets NHWC(18), 2 rows per block
// ---------------------------------------------------------------------------
__global__ void __launch_bounds__(256) conv_off_kernel(const float* __restrict__ ob) {
    __shared__ __align__(16) float sw[CC * 9 * OFFP];
    for (int idx = threadIdx.x; idx < CC * 9 * OFFP; idx += 256) sw[idx] = g_owT[idx];
    __syncthreads();

    const int b = blockIdx.x / (HH / 2);
    const int h0 = (blockIdx.x % (HH / 2)) * 2;
    const int w = threadIdx.x;

    ull accA[9], accB[9];
    #pragma unroll
    for (int q = 0; q < 9; q++) {
        ull t = pack2(ob[2 * q], ob[2 * q + 1]);
        accA[q] = t; accB[q] = t;
    }

    #pragma unroll 1
    for (int i = 0; i < 3; i++) {
        int yA = h0 - 1 + i, yB = h0 + i;
        bool yAv = ((unsigned)yA < HH), yBv = ((unsigned)yB < HH);
        #pragma unroll 1
        for (int j = 0; j < 3; j++) {
            int xx = w - 1 + j;
            bool xv = ((unsigned)xx < WW);
            bool vA = yAv && xv, vB = yBv && xv;
            int xc = xv ? xx : 0;
            int iA = (vA ? yA : 0) * WW + xc;
            int iB = (vB ? yB : 0) * WW + xc;
            const int tap = i * 3 + j;
            #pragma unroll 1
            for (int c4 = 0; c4 < NP; c4++) {
                const float4* pc = g_feat + (c4 * BB + b) * HH * WW;
                float4 fa = vA ? pc[iA] : make_float4(0.f, 0.f, 0.f, 0.f);
                float4 fb = vB ? pc[iB] : make_float4(0.f, 0.f, 0.f, 0.f);
                const float fav[4] = {fa.x, fa.y, fa.z, fa.w};
                const float fbv[4] = {fb.x, fb.y, fb.z, fb.w};
                #pragma unroll
                for (int cc = 0; cc < 4; cc++) {
                    ull sa = pack2(fav[cc], fav[cc]);
                    ull sb2 = pack2(fbv[cc], fbv[cc]);
                    const float* wrow = &sw[((c4 * 4 + cc) * 9 + tap) * OFFP];
                    const ulonglong2* wp = (const ulonglong2*)wrow;
                    #pragma unroll
                    for (int q2 = 0; q2 < 4; q2++) {
                        ulonglong2 ww = wp[q2];
                        FMA2(accA[2 * q2], sa, ww.x);
                        FMA2(accA[2 * q2 + 1], sa, ww.y);
                        FMA2(accB[2 * q2], sb2, ww.x);
                        FMA2(accB[2 * q2 + 1], sb2, ww.y);
                    }
                    ull w8 = *(const ull*)(wrow + 16);
                    FMA2(accA[8], sa, w8);
                    FMA2(accB[8], sb2, w8);
                }
            }
        }
    }

    float* opA = &g_off[((b * HH + h0) * WW + w) * OFFC];
    float* opB = opA + WW * OFFC;
    #pragma unroll
    for (int q = 0; q < 9; q++) {
        ((float2*)opA)[q] = unpack2(accA[q]);
        ((float2*)opB)[q] = unpack2(accB[q]);
    }
}

// ---------------------------------------------------------------------------
// Kernel 3: deform conv via mma.sync bf16 3-term split.
// 128 threads, 4 warps. Tile 128px x 64o, K=64c per tap.
// smem: Shi[128][64]bf16 16KB | Slo 16KB | Whi[64][64]bf16 8KB | Wlo 8KB = 48KB.
// Per tap: gather+bilinear+split -> swizzled S tiles; memcpy W tap tile;
// warp = 32px x 64o via 2x8 m16n8 mma blocks, k-loop of 4 k16 chunks.
// ---------------------------------------------------------------------------
#define SHI_OFF 0
#define SLO_OFF 16384
#define WHI_OFF 32768
#define WLO_OFF 40960

__device__ __forceinline__ void tap_coords(int h, int w_img, int kk, float2 o2,
                                           float& w00, float& w01, float& w10, float& w11,
                                           int& i00, int& i01, int& i10, int& i11) {
    const int i = kk / 3, j = kk - 3 * i;
    float sy = (float)(h - 1 + i) + o2.x;
    float sx = (float)(w_img - 1 + j) + o2.y;
    float y0f = floorf(sy), x0f = floorf(sx);
    float dy = sy - y0f, dx = sx - x0f;
    int y0 = (int)y0f, x0 = (int)x0f, y1 = y0 + 1, x1 = x0 + 1;
    bool vy0 = ((unsigned)y0 < HH), vy1 = ((unsigned)y1 < HH);
    bool vx0 = ((unsigned)x0 < WW), vx1 = ((unsigned)x1 < WW);
    w00 = (1.f - dy) * (1.f - dx) * ((vy0 && vx0) ? 1.f : 0.f);
    w01 = (1.f - dy) * dx         * ((vy0 && vx1) ? 1.f : 0.f);
    w10 = dy * (1.f - dx)         * ((vy1 && vx0) ? 1.f : 0.f);
    w11 = dy * dx                 * ((vy1 && vx1) ? 1.f : 0.f);
    int y0c = min(max(y0, 0), HH - 1), y1c = min(max(y1, 0), HH - 1);
    int x0c = min(max(x0, 0), WW - 1), x1c = min(max(x1, 0), WW - 1);
    i00 = y0c * WW + x0c; i01 = y0c * WW + x1c;
    i10 = y1c * WW + x0c; i11 = y1c * WW + x1c;
}

__global__ void __launch_bounds__(128, 3) deform_kernel(const float* __restrict__ db,
                                                        float* __restrict__ out) {
    extern __shared__ __align__(1024) char smem[];
    const uint32 sbase = smem_u32(smem);

    const int tid = threadIdx.x;
    const int lane = tid & 31;
    const int warp = tid >> 5;
    const int bi = blockIdx.x;
    const int b = bi >> 9;
    const int rest = bi & 511;
    const int h = rest >> 1;
    const int wbase = (rest & 1) << 7;

    const int px_g = tid;
    const int w_img = wbase + px_g;
    const float* offp = g_off + (((b * HH + h) * WW) + w_img) * OFFC;

    float acc[2][8][4];
    #pragma unroll
    for (int mb = 0; mb < 2; mb++)
        #pragma unroll
        for (int nb = 0; nb < 8; nb++)
            #pragma unroll
            for (int q = 0; q < 4; q++) acc[mb][nb][q] = 0.0f;

    // ldmatrix per-lane row/granule splits
    const uint32 aRow = warp * 32 + ((lane >> 3) & 1) * 8 + (lane & 7);
    const uint32 aGr  = (lane >> 4) & 1;
    const uint32 bRowOff = ((lane >> 4) & 1) * 8 + (lane & 7);
    const uint32 bGr  = (lane >> 3) & 1;

    // S store base (per-thread row px_g)
    const uint32 sRowSw = px_g & 7;
    char* sHiRow = smem + SHI_OFF + px_g * 128;
    char* sLoRow = smem + SLO_OFF + px_g * 128;

    #pragma unroll 1
    for (int k = 0; k < 9; k++) {
        __syncthreads();   // previous mma phase done reading tiles

        // -- W tap tile copy (pre-swizzled): 16KB --
        {
            const uint4* gWk = (const uint4*)(g_dwB + k * 16384);
            uint4* wd = (uint4*)(smem + WHI_OFF);
            #pragma unroll
            for (int q = 0; q < 8; q++) wd[q * 128 + tid] = gWk[q * 128 + tid];
        }
        // -- gather + bilinear + bf16 split into swizzled S tiles --
        {
            float2 o2 = __ldg((const float2*)(offp + 2 * k));
            float w00, w01, w10, w11; int i00, i01, i10, i11;
            tap_coords(h, w_img, k, o2, w00, w01, w10, w11, i00, i01, i10, i11);
            ull W00 = pack2(w00, w00), W01 = pack2(w01, w01);
            ull W10 = pack2(w10, w10), W11 = pack2(w11, w11);
            #pragma unroll
            for (int g = 0; g < 8; g++) {
                uint32 hv[4], lv[4];
                #pragma unroll
                for (int pp = 0; pp < 2; pp++) {
                    const int pl = g * 2 + pp;
                    const ulonglong2* pc = (const ulonglong2*)(g_feat + (pl * BB + b) * HH * WW);
                    ulonglong2 a = pc[i00], b2 = pc[i01], c2 = pc[i10], d2 = pc[i11];
                    ull s01, s23;
                    MUL2(s01, W00, a.x);
                    FMA2(s01, W01, b2.x); FMA2(s01, W10, c2.x); FMA2(s01, W11, d2.x);
                    MUL2(s23, W00, a.y);
                    FMA2(s23, W01, b2.y); FMA2(s23, W10, c2.y); FMA2(s23, W11, d2.y);
                    hv[2 * pp + 0] = bf_split(s01, lv[2 * pp + 0]);
                    hv[2 * pp + 1] = bf_split(s23, lv[2 * pp + 1]);
                }
                const int go = (g ^ sRowSw) * 16;
                *(uint4*)(sHiRow + go) = make_uint4(hv[0], hv[1], hv[2], hv[3]);
                *(uint4*)(sLoRow + go) = make_uint4(lv[0], lv[1], lv[2], lv[3]);
            }
        }
        __syncthreads();

        // -- mma phase: warp tile 32px x 64o, K=64 --
        #pragma unroll
        for (int kg2 = 0; kg2 < 4; kg2++) {
            uint32 ah[2][4], al[2][4];
            #pragma unroll
            for (int mb = 0; mb < 2; mb++) {
                uint32 r = aRow + mb * 16;
                uint32 g = 2 * kg2 + aGr;
                uint32 off = r * 128 + ((g ^ (r & 7)) * 16);
                uint32 addrH = sbase + SHI_OFF + off;
                uint32 addrL = sbase + SLO_OFF + off;
                LDMX4(ah[mb][0], ah[mb][1], ah[mb][2], ah[mb][3], addrH);
                LDMX4(al[mb][0], al[mb][1], al[mb][2], al[mb][3], addrL);
            }
            #pragma unroll
            for (int nb2 = 0; nb2 < 4; nb2++) {
                uint32 bh[4], bl[4];
                uint32 rB = nb2 * 16 + bRowOff;
                uint32 gB = 2 * kg2 + bGr;
                uint32 offB = rB * 128 + ((gB ^ (rB & 7)) * 16);
                LDMX4(bh[0], bh[1], bh[2], bh[3], sbase + WHI_OFF + offB);
                LDMX4(bl[0], bl[1], bl[2], bl[3], sbase + WLO_OFF + offB);
                #pragma unroll
                for (int mb = 0; mb < 2; mb++) {
                    float* dLo = acc[mb][nb2 * 2];
                    float* dHi = acc[mb][nb2 * 2 + 1];
                    // hi x hi
                    MMA_BF16(dLo, ah[mb][0], ah[mb][1], bh[0]);
                    MMA_BF16(dLo, ah[mb][2], ah[mb][3], bh[1]);
                    MMA_BF16(dHi, ah[mb][0], ah[mb][1], bh[2]);
                    MMA_BF16(dHi, ah[mb][2], ah[mb][3], bh[3]);
                    // hi x lo
                    MMA_BF16(dLo, ah[mb][0], ah[mb][1], bl[0]);
                    MMA_BF16(dLo, ah[mb][2], ah[mb][3], bl[1]);
                    MMA_BF16(dHi, ah[mb][0], ah[mb][1], bl[2]);
                    MMA_BF16(dHi, ah[mb][2], ah[mb][3], bl[3]);
                    // lo x hi
                    MMA_BF16(dLo, al[mb][0], al[mb][1], bh[0]);
                    MMA_BF16(dLo, al[mb][2], al[mb][3], bh[1]);
                    MMA_BF16(dHi, al[mb][0], al[mb][1], bh[2]);
                    MMA_BF16(dHi, al[mb][2], al[mb][3], bh[3]);
                }
            }
        }
    }

    // Epilogue: add bias, write NCHW from mma fragments
    const int cpos = (lane & 3) * 2;
    const int rpos = lane >> 2;
    #pragma unroll
    for (int nb = 0; nb < 8; nb++) {
        const int o0 = nb * 8 + cpos;
        float b0 = __ldg(db + o0), b1 = __ldg(db + o0 + 1);
        #pragma unroll
        for (int mb = 0; mb < 2; mb++) {
            const int px = warp * 32 + mb * 16 + rpos;
            const int base0 = ((b * CC + o0) * HH + h) * WW + wbase + px;
            out[base0]               = acc[mb][nb][0] + b0;
            out[base0 + HH * WW]     = acc[mb][nb][1] + b1;
            out[base0 + 8]           = acc[mb][nb][2] + b0;
            out[base0 + HH * WW + 8] = acc[mb][nb][3] + b1;
        }
    }
}

// ---------------------------------------------------------------------------
extern "C" void kernel_launch(void* const* d_in, const int* in_sizes, int n_in,
                              void* d_out, int out_size) {
    const float* x        = (const float*)d_in[0];
    const float* conv_w   = (const float*)d_in[1];
    const float* conv_b   = (const float*)d_in[2];
    const float* offset_w = (const float*)d_in[3];
    const float* offset_b = (const float*)d_in[4];
    const float* deform_w = (const float*)d_in[5];
    const float* deform_b = (const float*)d_in[6];
    float* out = (float*)d_out;

    const int dsm = 49152;   // 48KB
    cudaFuncSetAttribute(deform_kernel, cudaFuncAttributeMaxDynamicSharedMemorySize, dsm);

    prep_kernel<<<96, 512>>>(conv_w, offset_w, deform_w);
    conv_in_kernel<<<BB * HH, 256>>>(x, conv_b);
    conv_off_kernel<<<BB * HH / 2, 256>>>(offset_b);
    deform_kernel<<<BB * HH * 2, 128, dsm>>>(deform_b, out);
}

// round 16
// speedup vs baseline: 1.9550x; 1.0497x over previous
#include <cuda_runtime.h>
#include <cstdint>

#define BB   4
#define HH   256
#define WW   256
#define CC   64
#define CIN  3
#define OFFC 18
#define OFFP 20
#define NP   16

// Scratch (allocation-free)
__device__ float4 g_feat[NP * BB * HH * WW];       // NC4HW4 features
__device__ float  g_off [BB * HH * WW * OFFC];     // NHWC offsets
__device__ float  g_cwT [CIN * 9 * CC];
__device__ float  g_owT [CC * 9 * OFFP];
__device__ unsigned char g_dwB[9 * 16384];         // per tap: 8KB Whi + 8KB Wlo bf16, swizzled

typedef unsigned long long ull;
typedef unsigned int uint32;

__device__ __forceinline__ ull pack2(float lo, float hi) {
    ull r; asm("mov.b64 %0, {%1,%2};" : "=l"(r) : "f"(lo), "f"(hi)); return r;
}
__device__ __forceinline__ float2 unpack2(ull v) {
    float2 r; asm("mov.b64 {%0,%1}, %2;" : "=f"(r.x), "=f"(r.y) : "l"(v)); return r;
}
#define FMA2(a, x, y) asm("fma.rn.f32x2 %0, %1, %2, %0;" : "+l"(a) : "l"(x), "l"(y))
#define MUL2(a, x, y) asm("mul.rn.f32x2 %0, %1, %2;" : "=l"(a) : "l"(x), "l"(y))

__device__ __forceinline__ uint32 smem_u32(const void* p) {
    uint32 a;
    asm("{ .reg .u64 t; cvta.to.shared.u64 t, %1; cvt.u32.u64 %0, t; }" : "=r"(a) : "l"(p));
    return a;
}

#define LDMX4(r0, r1, r2, r3, addr) \
    asm volatile("ldmatrix.sync.aligned.m8n8.x4.shared.b16 {%0,%1,%2,%3}, [%4];" \
                 : "=r"(r0), "=r"(r1), "=r"(r2), "=r"(r3) : "r"(addr))

#define MMA_BF16(d, a0, a1, b0) \
    asm volatile("mma.sync.aligned.m16n8k8.row.col.f32.bf16.bf16.f32 " \
                 "{%0,%1,%2,%3}, {%4,%5}, {%6}, {%0,%1,%2,%3};" \
                 : "+f"((d)[0]), "+f"((d)[1]), "+f"((d)[2]), "+f"((d)[3]) \
                 : "r"(a0), "r"(a1), "r"(b0))

// split packed f32x2 -> bf16x2 hi + bf16x2 lo
__device__ __forceinline__ uint32 bf_split(ull s, uint32& lo) {
    float2 f = unpack2(s);
    uint32 h;
    asm("cvt.rn.bf16x2.f32 %0, %1, %2;" : "=r"(h) : "f"(f.y), "f"(f.x));
    float hf0 = __uint_as_float(h << 16);
    float hf1 = __uint_as_float(h & 0xffff0000u);
    float l0 = f.x - hf0, l1 = f.y - hf1;
    asm("cvt.rn.bf16x2.f32 %0, %1, %2;" : "=r"(lo) : "f"(l1), "f"(l0));
    return h;
}

// ---------------------------------------------------------------------------
__global__ void prep_kernel(const float* __restrict__ cw,
                            const float* __restrict__ ow,
                            const float* __restrict__ dw) {
    int t = blockIdx.x * blockDim.x + threadIdx.x;
    int nt = gridDim.x * blockDim.x;
    for (int idx = t; idx < CIN * 9 * CC; idx += nt) {
        int o = idx % CC, r = idx / CC;
        g_cwT[idx] = cw[o * (CIN * 9) + r];
    }
    for (int idx = t; idx < CC * 9 * OFFP; idx += nt) {
        int oc = idx % OFFP, ct = idx / OFFP;
        g_owT[idx] = (oc < OFFC) ? ow[oc * (CC * 9) + ct] : 0.0f;
    }
    // deform weights -> bf16 hi/lo tiles [k][o row][c col], 16B-granule swizzle
    for (int idx = t; idx < 9 * CC * CC; idx += nt) {
        int k = idx / (CC * CC), r = idx % (CC * CC);
        int o = r / CC, c = r % CC;
        float wv = dw[(o * CC + c) * 9 + k];
        uint32 hb;
        asm("cvt.rn.bf16x2.f32 %0, %1, %2;" : "=r"(hb) : "f"(0.0f), "f"(wv));
        float hf = __uint_as_float(hb << 16);
        float lv = wv - hf;
        uint32 lb;
        asm("cvt.rn.bf16x2.f32 %0, %1, %2;" : "=r"(lb) : "f"(0.0f), "f"(lv));
        int g = c >> 3;
        int byte = o * 128 + ((g ^ (o & 7)) * 16) + (c & 7) * 2;
        *(unsigned short*)(g_dwB + k * 16384 + byte) = (unsigned short)(hb & 0xffff);
        *(unsigned short*)(g_dwB + k * 16384 + 8192 + byte) = (unsigned short)(lb & 0xffff);
    }
}

// ---------------------------------------------------------------------------
// Kernel 1: x NCHW -> feat NC4HW4, 3x3 conv pad 1
// ---------------------------------------------------------------------------
__global__ void __launch_bounds__(256) conv_in_kernel(const float* __restrict__ x,
                                                      const float* __restrict__ cb) {
    __shared__ __align__(16) float sw[CIN * 9 * CC];
    __shared__ float sb[CC];
    for (int idx = threadIdx.x; idx < CIN * 9 * CC; idx += 256) sw[idx] = g_cwT[idx];
    if (threadIdx.x < CC) sb[threadIdx.x] = cb[threadIdx.x];
    __syncthreads();

    const int b = blockIdx.x / HH, h = blockIdx.x % HH, w = threadIdx.x;

    ull acc[32];
    #pragma unroll
    for (int q = 0; q < 32; q++) acc[q] = pack2(sb[2 * q], sb[2 * q + 1]);

    #pragma unroll 1
    for (int ci = 0; ci < CIN; ci++) {
        #pragma unroll
        for (int i = 0; i < 3; i++) {
            int y = h - 1 + i;
            bool yv = ((unsigned)y < HH);
            #pragma unroll
            for (int j = 0; j < 3; j++) {
                int xx = w - 1 + j;
                float v = (yv && (unsigned)xx < WW) ? x[((b * CIN + ci) * HH + y) * WW + xx] : 0.0f;
                ull s2 = pack2(v, v);
                const ulonglong2* wp = (const ulonglong2*)&sw[(ci * 9 + i * 3 + j) * CC];
                #pragma unroll
                for (int q = 0; q < 16; q++) {
                    ulonglong2 ww = wp[q];
                    FMA2(acc[2 * q], s2, ww.x);
                    FMA2(acc[2 * q + 1], s2, ww.y);
                }
            }
        }
    }

    const int ppix = h * WW + w;
    #pragma unroll
    for (int q4 = 0; q4 < NP; q4++) {
        float2 lo = unpack2(acc[2 * q4]);
        float2 hi = unpack2(acc[2 * q4 + 1]);
        g_feat[(q4 * BB + b) * HH * WW + ppix] = make_float4(lo.x, lo.y, hi.x, hi.y);
    }
}

// ---------------------------------------------------------------------------
// Kernel 2: feat NC4HW4 -> offsets NHWC(18), 2 rows per block
// ---------------------------------------------------------------------------
__global__ void __launch_bounds__(256) conv_off_kernel(const float* __restrict__ ob) {
    __shared__ __align__(16) float sw[CC * 9 * OFFP];
    for (int idx = threadIdx.x; idx < CC * 9 * OFFP; idx += 256) sw[idx] = g_owT[idx];
    __syncthreads();

    const int b = blockIdx.x / (HH / 2);
    const int h0 = (blockIdx.x % (HH / 2)) * 2;
    const int w = threadIdx.x;

    ull accA[9], accB[9];
    #pragma unroll
    for (int q = 0; q < 9; q++) {
        ull t = pack2(ob[2 * q], ob[2 * q + 1]);
        accA[q] = t; accB[q] = t;
    }

    #pragma unroll 1
    for (int i = 0; i < 3; i++) {
        int yA = h0 - 1 + i, yB = h0 + i;
        bool yAv = ((unsigned)yA < HH), yBv = ((unsigned)yB < HH);
        #pragma unroll 1
        for (int j = 0; j < 3; j++) {
            int xx = w - 1 + j;
            bool xv = ((unsigned)xx < WW);
            bool vA = yAv && xv, vB = yBv && xv;
            int xc = xv ? xx : 0;
            int iA = (vA ? yA : 0) * WW + xc;
            int iB = (vB ? yB : 0) * WW + xc;
            const int tap = i * 3 + j;
            #pragma unroll 1
            for (int c4 = 0; c4 < NP; c4++) {
                const float4* pc = g_feat + (c4 * BB + b) * HH * WW;
                float4 fa = vA ? pc[iA] : make_float4(0.f, 0.f, 0.f, 0.f);
                float4 fb = vB ? pc[iB] : make_float4(0.f, 0.f, 0.f, 0.f);
                const float fav[4] = {fa.x, fa.y, fa.z, fa.w};
                const float fbv[4] = {fb.x, fb.y, fb.z, fb.w};
                #pragma unroll
                for (int cc = 0; cc < 4; cc++) {
                    ull sa = pack2(fav[cc], fav[cc]);
                    ull sb2 = pack2(fbv[cc], fbv[cc]);
                    const float* wrow = &sw[((c4 * 4 + cc) * 9 + tap) * OFFP];
                    const ulonglong2* wp = (const ulonglong2*)wrow;
                    #pragma unroll
                    for (int q2 = 0; q2 < 4; q2++) {
                        ulonglong2 ww = wp[q2];
                        FMA2(accA[2 * q2], sa, ww.x);
                        FMA2(accA[2 * q2 + 1], sa, ww.y);
                        FMA2(accB[2 * q2], sb2, ww.x);
                        FMA2(accB[2 * q2 + 1], sb2, ww.y);
                    }
                    ull w8 = *(const ull*)(wrow + 16);
                    FMA2(accA[8], sa, w8);
                    FMA2(accB[8], sb2, w8);
                }
            }
        }
    }

    float* opA = &g_off[((b * HH + h0) * WW + w) * OFFC];
    float* opB = opA + WW * OFFC;
    #pragma unroll
    for (int q = 0; q < 9; q++) {
        ((float2*)opA)[q] = unpack2(accA[q]);
        ((float2*)opB)[q] = unpack2(accB[q]);
    }
}

// ---------------------------------------------------------------------------
// Kernel 3: deform conv via mma.sync bf16 3-term split, software-pipelined.
// 128 threads, 4 warps. Double-buffered S (hi/lo) + W: 96KB, 2 CTAs/SM.
// Per tap k: mma on buf[k&1] interleaved (per kg chunk) with gather of tap
// k+1 into buf[(k+1)&1]. One __syncthreads per tap.
// ---------------------------------------------------------------------------
#define SBUF(buf)  ((buf) * 32768)           // Shi at +0, Slo at +16384
#define WBUF(buf)  (65536 + (buf) * 16384)
#define DSMEM      98304

__device__ __forceinline__ void tap_coords(int h, int w_img, int kk, float2 o2,
                                           float& w00, float& w01, float& w10, float& w11,
                                           int& i00, int& i01, int& i10, int& i11) {
    const int i = kk / 3, j = kk - 3 * i;
    float sy = (float)(h - 1 + i) + o2.x;
    float sx = (float)(w_img - 1 + j) + o2.y;
    float y0f = floorf(sy), x0f = floorf(sx);
    float dy = sy - y0f, dx = sx - x0f;
    int y0 = (int)y0f, x0 = (int)x0f, y1 = y0 + 1, x1 = x0 + 1;
    bool vy0 = ((unsigned)y0 < HH), vy1 = ((unsigned)y1 < HH);
    bool vx0 = ((unsigned)x0 < WW), vx1 = ((unsigned)x1 < WW);
    w00 = (1.f - dy) * (1.f - dx) * ((vy0 && vx0) ? 1.f : 0.f);
    w01 = (1.f - dy) * dx         * ((vy0 && vx1) ? 1.f : 0.f);
    w10 = dy * (1.f - dx)         * ((vy1 && vx0) ? 1.f : 0.f);
    w11 = dy * dx                 * ((vy1 && vx1) ? 1.f : 0.f);
    int y0c = min(max(y0, 0), HH - 1), y1c = min(max(y1, 0), HH - 1);
    int x0c = min(max(x0, 0), WW - 1), x1c = min(max(x1, 0), WW - 1);
    i00 = y0c * WW + x0c; i01 = y0c * WW + x1c;
    i10 = y1c * WW + x0c; i11 = y1c * WW + x1c;
}

// gather+bilinear+split 2 plane-group (4 planes = 8 channels) -> swizzled S tiles
__device__ __forceinline__ void gather_group(char* sHiRow, char* sLoRow, int go,
                                             int g, int b,
                                             int i00, int i01, int i10, int i11,
                                             ull W00, ull W01, ull W10, ull W11) {
    uint32 hv[4], lv[4];
    #pragma unroll
    for (int pp = 0; pp < 2; pp++) {
        const int pl = g * 2 + pp;
        const ulonglong2* pc = (const ulonglong2*)(g_feat + (pl * BB + b) * HH * WW);
        ulonglong2 a = pc[i00], b2 = pc[i01], c2 = pc[i10], d2 = pc[i11];
        ull s01, s23;
        MUL2(s01, W00, a.x);
        FMA2(s01, W01, b2.x); FMA2(s01, W10, c2.x); FMA2(s01, W11, d2.x);
        MUL2(s23, W00, a.y);
        FMA2(s23, W01, b2.y); FMA2(s23, W10, c2.y); FMA2(s23, W11, d2.y);
        hv[2 * pp + 0] = bf_split(s01, lv[2 * pp + 0]);
        hv[2 * pp + 1] = bf_split(s23, lv[2 * pp + 1]);
    }
    *(uint4*)(sHiRow + go) = make_uint4(hv[0], hv[1], hv[2], hv[3]);
    *(uint4*)(sLoRow + go) = make_uint4(lv[0], lv[1], lv[2], lv[3]);
}

__global__ void __launch_bounds__(128, 2) deform_kernel(const float* __restrict__ db,
                                                        float* __restrict__ out) {
    extern __shared__ __align__(1024) char smem[];
    const uint32 sbase = smem_u32(smem);

    const int tid = threadIdx.x;
    const int lane = tid & 31;
    const int warp = tid >> 5;
    const int bi = blockIdx.x;
    const int b = bi >> 9;
    const int rest = bi & 511;
    const int h = rest >> 1;
    const int wbase = (rest & 1) << 7;

    const int px_g = tid;
    const int w_img = wbase + px_g;
    const float* offp = g_off + (((b * HH + h) * WW) + w_img) * OFFC;

    float acc[2][8][4];
    #pragma unroll
    for (int mb = 0; mb < 2; mb++)
        #pragma unroll
        for (int nb = 0; nb < 8; nb++)
            #pragma unroll
            for (int q = 0; q < 4; q++) acc[mb][nb][q] = 0.0f;

    // ldmatrix per-lane row/granule splits
    const uint32 aRow = warp * 32 + ((lane >> 3) & 1) * 8 + (lane & 7);
    const uint32 aGr  = (lane >> 4) & 1;
    const uint32 bRowOff = ((lane >> 4) & 1) * 8 + (lane & 7);
    const uint32 bGr  = (lane >> 3) & 1;

    const uint32 sRowSw = px_g & 7;

    // Prologue: W(0) copy + gather tap 0 into buffer 0
    {
        const uint4* gWk = (const uint4*)(g_dwB);
        uint4* wd = (uint4*)(smem + WBUF(0));
        #pragma unroll
        for (int q = 0; q < 8; q++) wd[q * 128 + tid] = gWk[q * 128 + tid];

        float2 o2 = __ldg((const float2*)offp);
        float w00, w01, w10, w11; int i00, i01, i10, i11;
        tap_coords(h, w_img, 0, o2, w00, w01, w10, w11, i00, i01, i10, i11);
        ull W00 = pack2(w00, w00), W01 = pack2(w01, w01);
        ull W10 = pack2(w10, w10), W11 = pack2(w11, w11);
        char* sHiRow = smem + SBUF(0) + px_g * 128;
        char* sLoRow = smem + SBUF(0) + 16384 + px_g * 128;
        #pragma unroll
        for (int g = 0; g < 8; g++)
            gather_group(sHiRow, sLoRow, (g ^ sRowSw) * 16, g, b, i00, i01, i10, i11,
                         W00, W01, W10, W11);
    }
    __syncthreads();

    #pragma unroll 1
    for (int k = 0; k < 9; k++) {
        const int rb = k & 1;         // read buffer
        const int wb = rb ^ 1;        // write buffer
        const uint32 sHiB = sbase + SBUF(rb);
        const uint32 sLoB = sHiB + 16384;
        const uint32 wHiB = sbase + WBUF(rb);
        const uint32 wLoB = wHiB + 8192;

        const int kk = k + 1;
        const bool dog = (kk < 9);

        // next-tap coords + W copy kickoff
        ull W00 = 0, W01 = 0, W10 = 0, W11 = 0;
        int i00 = 0, i01 = 0, i10 = 0, i11 = 0;
        char* sHiRowD = smem + SBUF(wb) + px_g * 128;
        char* sLoRowD = smem + SBUF(wb) + 16384 + px_g * 128;
        if (dog) {
            float2 o2 = __ldg((const float2*)(offp + 2 * kk));
            float w00f, w01f, w10f, w11f;
            tap_coords(h, w_img, kk, o2, w00f, w01f, w10f, w11f, i00, i01, i10, i11);
            W00 = pack2(w00f, w00f); W01 = pack2(w01f, w01f);
            W10 = pack2(w10f, w10f); W11 = pack2(w11f, w11f);
            const uint4* gWk = (const uint4*)(g_dwB + kk * 16384);
            uint4* wd = (uint4*)(smem + WBUF(wb));
            #pragma unroll
            for (int q = 0; q < 8; q++) wd[q * 128 + tid] = gWk[q * 128 + tid];
        }

        // mma phase interleaved with next-tap gather (per kg chunk)
        #pragma unroll
        for (int kg2 = 0; kg2 < 4; kg2++) {
            uint32 ah[2][4], al[2][4];
            #pragma unroll
            for (int mb = 0; mb < 2; mb++) {
                uint32 r = aRow + mb * 16;
                uint32 g = 2 * kg2 + aGr;
                uint32 off = r * 128 + ((g ^ (r & 7)) * 16);
                LDMX4(ah[mb][0], ah[mb][1], ah[mb][2], ah[mb][3], sHiB + off);
                LDMX4(al[mb][0], al[mb][1], al[mb][2], al[mb][3], sLoB + off);
            }
            #pragma unroll
            for (int nb2 = 0; nb2 < 4; nb2++) {
                uint32 bh[4], bl[4];
                uint32 rB = nb2 * 16 + bRowOff;
                uint32 gB = 2 * kg2 + bGr;
                uint32 offB = rB * 128 + ((gB ^ (rB & 7)) * 16);
                LDMX4(bh[0], bh[1], bh[2], bh[3], wHiB + offB);
                LDMX4(bl[0], bl[1], bl[2], bl[3], wLoB + offB);
                #pragma unroll
                for (int mb = 0; mb < 2; mb++) {
                    float* dLo = acc[mb][nb2 * 2];
                    float* dHi = acc[mb][nb2 * 2 + 1];
                    MMA_BF16(dLo, ah[mb][0], ah[mb][1], bh[0]);
                    MMA_BF16(dLo, ah[mb][2], ah[mb][3], bh[1]);
                    MMA_BF16(dHi, ah[mb][0], ah[mb][1], bh[2]);
                    MMA_BF16(dHi, ah[mb][2], ah[mb][3], bh[3]);
                    MMA_BF16(dLo, ah[mb][0], ah[mb][1], bl[0]);
                    MMA_BF16(dLo, ah[mb][2], ah[mb][3], bl[1]);
                    MMA_BF16(dHi, ah[mb][0], ah[mb][1], bl[2]);
                    MMA_BF16(dHi, ah[mb][2], ah[mb][3], bl[3]);
                    MMA_BF16(dLo, al[mb][0], al[mb][1], bh[0]);
                    MMA_BF16(dLo, al[mb][2], al[mb][3], bh[1]);
                    MMA_BF16(dHi, al[mb][0], al[mb][1], bh[2]);
                    MMA_BF16(dHi, al[mb][2], al[mb][3], bh[3]);
                }
            }
            // gather 2 plane-groups (4 planes) of tap k+1 into write buffer
            if (dog) {
                #pragma unroll
                for (int gg = 0; gg < 2; gg++) {
                    const int g = 2 * kg2 + gg;
                    gather_group(sHiRowD, sLoRowD, (g ^ sRowSw) * 16, g, b,
                                 i00, i01, i10, i11, W00, W01, W10, W11);
                }
            }
        }
        __syncthreads();
    }

    // Epilogue: add bias, write NCHW from mma fragments
    const int cpos = (lane & 3) * 2;
    const int rpos = lane >> 2;
    #pragma unroll
    for (int nb = 0; nb < 8; nb++) {
        const int o0 = nb * 8 + cpos;
        float b0 = __ldg(db + o0), b1 = __ldg(db + o0 + 1);
        #pragma unroll
        for (int mb = 0; mb < 2; mb++) {
            const int px = warp * 32 + mb * 16 + rpos;
            const int base0 = ((b * CC + o0) * HH + h) * WW + wbase + px;
            out[base0]               = acc[mb][nb][0] + b0;
            out[base0 + HH * WW]     = acc[mb][nb][1] + b1;
            out[base0 + 8]           = acc[mb][nb][2] + b0;
            out[base0 + HH * WW + 8] = acc[mb][nb][3] + b1;
        }
    }
}

// ---------------------------------------------------------------------------
extern "C" void kernel_launch(void* const* d_in, const int* in_sizes, int n_in,
                              void* d_out, int out_size) {
    const float* x        = (const float*)d_in[0];
    const float* conv_w   = (const float*)d_in[1];
    const float* conv_b   = (const float*)d_in[2];
    const float* offset_w = (const float*)d_in[3];
    const float* offset_b = (const float*)d_in[4];
    const float* deform_w = (const float*)d_in[5];
    const float* deform_b = (const float*)d_in[6];
    float* out = (float*)d_out;

    cudaFuncSetAttribute(deform_kernel, cudaFuncAttributeMaxDynamicSharedMemorySize, DSMEM);

    prep_kernel<<<96, 512>>>(conv_w, offset_w, deform_w);
    conv_in_kernel<<<BB * HH, 256>>>(x, conv_b);
    conv_off_kernel<<<BB * HH / 2, 256>>>(offset_b);
    deform_kernel<<<BB * HH * 2, 128, DSMEM>>>(deform_b, out);
}